// round 5
// baseline (speedup 1.0000x reference)
#include <cuda_runtime.h>
#include <math.h>

#define GSZ 32
#define LL  1024
#define BB  4
#define NNB 20
#define BP  (BB*NNB)     // 80
#define CC  128
#define HH  8
#define WW  32
#define HW  256
#define NRAY 360
#define NI   384         // padded ind count (12 tiles of 32)

// packed f32x2 FMA (Blackwell): one inst = 2 fp32 FMAs
#define FMA_F32X2(d,a,b,c) asm("fma.rn.f32x2 %0, %1, %2, %3;" : "=l"(d) : "l"(a), "l"(b), "l"(c))

// ---------------- scratch (device globals; no allocations) ----------------
__device__ float g_eR [NRAY*HW];
__device__ float g_eRT[HW*NI];          // [hw][ind], cols 360..383 garbage (never read)
__device__ float g_eP [BP*HW];
__device__ float g_ePT[HW*BP];          // [hw][bp]
__device__ float g_T  [NI*BP];          // [ind][bp], rows >=360 garbage (never read)
__device__ float g_G[(size_t)BP*NRAY*CC];   // 14.7 MB
__device__ int   g_ind[BB*LL*NNB];
__device__ float g_eD [BB*LL*NNB];
__device__ float g_invZ[BB*LL];

// ---------------- merged R/P tables: circular convs + fused exp ------------
// ray branch (blocks 0..359):   eR[ind,hw] = exp(conv(rays[ind]))
// pano branch (blocks 360..439): eP[bp,hw] = exp(conv(pano(feats[bp])))
__global__ void k_RP(const float* __restrict__ rays, const float* __restrict__ feats,
                     const float* __restrict__ w1, const float* __restrict__ w2,
                     const float* __restrict__ fw) {
    __shared__ float sbuf[3*HW];
    __shared__ float sw1[27], sw2[75];
    int t = threadIdx.x;
    int y = t >> 5, x = t & 31;

    if (blockIdx.x < NRAY) {
        int ind = blockIdx.x;
        for (int i = t; i < 3*HW; i += 256) sbuf[i] = rays[(size_t)ind*3*HW + i];
        if (t < 27) sw1[t] = w1[9  + t];   // conv1 channels 1..3
        if (t < 75) sw2[t] = w2[25 + t];   // conv2 channels 1..3
        __syncthreads();
        float a1 = 0.f, a2 = 0.f;
        #pragma unroll
        for (int c = 0; c < 3; c++) {
            const float* rc = sbuf + c*HW;
            #pragma unroll
            for (int ky = 0; ky < 3; ky++) {
                int yy = ((y + ky + 7) & 7) * 32;
                #pragma unroll
                for (int kx = 0; kx < 3; kx++)
                    a1 = fmaf(sw1[c*9 + ky*3 + kx], rc[yy + ((x + kx + 31) & 31)], a1);
            }
            #pragma unroll
            for (int ky = 0; ky < 5; ky++) {
                int yy = ((y + ky + 6) & 7) * 32;
                #pragma unroll
                for (int kx = 0; kx < 5; kx++)
                    a2 = fmaf(sw2[c*25 + ky*5 + kx], rc[yy + ((x + kx + 30) & 31)], a2);
            }
        }
        float e = expf(fw[0]*a1 + fw[1]*a2);
        g_eR [ind*HW + t]  = e;
        g_eRT[t*NI + ind]  = e;
    } else {
        int bp = blockIdx.x - NRAY;
        // pano: per-hw max/mean over C (reads feats directly)
        {
            const float* base = feats + (size_t)bp*CC*HW + t;
            float mx = -3.4e38f, sm = 0.f;
            #pragma unroll 8
            for (int c = 0; c < CC; c++) {
                float v = base[(size_t)c*HW];
                mx = fmaxf(mx, v);
                sm += v;
            }
            sbuf[t]      = mx;
            sbuf[HW + t] = sm * (1.0f/128.0f);
        }
        if (t < 18) sw1[t] = w1[4*9  + t];  // conv1 channels 4..5
        if (t < 50) sw2[t] = w2[4*25 + t];  // conv2 channels 4..5
        __syncthreads();
        float a1 = 0.f, a2 = 0.f;
        #pragma unroll
        for (int m = 0; m < 2; m++) {
            const float* pc = sbuf + m*HW;
            #pragma unroll
            for (int ky = 0; ky < 3; ky++) {
                int yy = ((y + ky + 7) & 7) * 32;
                #pragma unroll
                for (int kx = 0; kx < 3; kx++)
                    a1 = fmaf(sw1[m*9 + ky*3 + kx], pc[yy + ((x + kx + 31) & 31)], a1);
            }
            #pragma unroll
            for (int ky = 0; ky < 5; ky++) {
                int yy = ((y + ky + 6) & 7) * 32;
                #pragma unroll
                for (int kx = 0; kx < 5; kx++)
                    a2 = fmaf(sw2[m*25 + ky*5 + kx], pc[yy + ((x + kx + 30) & 31)], a2);
            }
        }
        float e = expf(fw[0]*a1 + fw[1]*a2);
        g_eP [bp*HW + t]  = e;
        g_ePT[t*BP + bp]  = e;
    }
}

// ---------------- T GEMM: T[ind,bp] = sum_hw eR[ind,hw]*eP[bp,hw] ----------
#define TTK 32
__global__ __launch_bounds__(256) void k_T() {
    __shared__ float sR[TTK][32];
    __shared__ float sP[TTK][BP];
    int ind0 = blockIdx.x * 32;
    int tid = threadIdx.x;
    int ti = tid & 31, gq = tid >> 5;       // 32 inds x 8 bp-groups of 10
    float acc[10];
    #pragma unroll
    for (int j = 0; j < 10; j++) acc[j] = 0.f;

    for (int k0 = 0; k0 < HW; k0 += TTK) {
        {   // sR: 32x32 floats = 256 float4
            int kk = tid >> 3, q = tid & 7;
            *(float4*)&sR[kk][q*4] = *(const float4*)&g_eRT[(size_t)(k0+kk)*NI + ind0 + q*4];
        }
        // sP: 32x80 floats = 640 float4
        for (int i = tid; i < TTK*(BP/4); i += 256) {
            int kk = i / (BP/4), q = i % (BP/4);
            *(float4*)&sP[kk][q*4] = *(const float4*)&g_ePT[(size_t)(k0+kk)*BP + q*4];
        }
        __syncthreads();
        #pragma unroll
        for (int kk = 0; kk < TTK; kk++) {
            float a = sR[kk][ti];
            #pragma unroll
            for (int j = 0; j < 10; j++)
                acc[j] = fmaf(a, sP[kk][gq*10 + j], acc[j]);
        }
        __syncthreads();
    }
    #pragma unroll
    for (int j = 0; j < 10; j++)
        g_T[(ind0 + ti)*BP + gq*10 + j] = acc[j];
}

// ---------------- geometry: ind, eD, Z per (b,s,p) --------------------------
__global__ void k_geo(const float* __restrict__ bbox, const float* __restrict__ locs,
                      const float* __restrict__ w1, const float* __restrict__ w2,
                      const float* __restrict__ fw) {
    int b = blockIdx.y;
    int s = blockIdx.x * 256 + threadIdx.x;
    int t = threadIdx.x;
    __shared__ float sT[NRAY*NNB];   // [ind][p]
    __shared__ float sl[NNB*2];
    __shared__ float sb[4];
    __shared__ float salpha;
    for (int i = t; i < NRAY*NNB; i += 256) {
        int ind = i / NNB, p = i % NNB;
        sT[i] = g_T[ind*BP + b*NNB + p];
    }
    if (t < NNB*2) sl[t] = locs[b*NNB*2 + t];
    if (t < 4)     sb[t] = bbox[b*4 + t];
    if (t == 0) {
        float s1 = 0.f, s2 = 0.f;
        for (int i = 0; i < 9; i++)  s1 += w1[i];
        for (int i = 0; i < 25; i++) s2 += w2[i];
        salpha = fw[0]*s1 + fw[1]*s2;
    }
    __syncthreads();
    int iy = s >> 5, ix = s & 31;
    float ystep = __fdiv_rn(sb[2] - sb[0], 31.0f);
    float xstep = __fdiv_rn(sb[3] - sb[1], 31.0f);
    float py = __fadd_rn(sb[0], __fmul_rn((float)iy, ystep));
    float px = __fadd_rn(sb[1], __fmul_rn((float)ix, xstep));
    float alpha = salpha;
    float Z = 0.f;
    int base = (b*LL + s)*NNB;
    for (int p = 0; p < NNB; p++) {
        float dy = py - sl[2*p];
        float dx = px - sl[2*p + 1];
        float D = sqrtf(__fadd_rn(__fadd_rn(__fmul_rn(dy,dy), __fmul_rn(dx,dx)), 1e-12f));
        float th = atan2f(dx, dy);
        if (th < 0.f) th += 6.283185307179586f;
        float deg = __fmul_rn(th, 57.29577951308232f);
        int ind = (int)rintf(deg);
        if (ind >= 360) ind -= 360;
        float eD = expf(alpha * D);
        g_ind[base + p] = ind;
        g_eD[base + p]  = eD;
        Z = fmaf(eD, sT[ind*NNB + p], Z);
    }
    g_invZ[b*LL + s] = 1.0f / Z;
}

// ---------------- G GEMM (FFMA2, double-buffered) ---------------------------
// G[bp, ind, f] = sum_hw eR[ind,hw] * feats[bp,f,hw] * eP[bp,hw]
#define TM 64
#define TN 128
#define TK 16
#define AROW (TM*2 + 4)
__global__ __launch_bounds__(256) void k_gemmG(const float* __restrict__ feats) {
    int m0 = blockIdx.x * TM;                  // ind tile
    int bp = blockIdx.z * NNB + blockIdx.y;    // (b,p)
    const float* fbase = feats + (size_t)bp*CC*HW;
    const float* epb   = g_eP + bp*HW;
    __shared__ __align__(16) float As2[2][TK][AROW];   // duplicated (a,a) pairs
    __shared__ __align__(16) float Bs[2][TK][TN];
    int tid = threadIdx.x;
    int tx = tid & 15;
    int ty = tid >> 4;
    int a_mi = tid >> 2, a_kq = tid & 3;
    int b_fi = tid >> 1, b_kq = tid & 1;

    unsigned long long acc[4][4];
    #pragma unroll
    for (int i = 0; i < 4; i++)
        #pragma unroll
        for (int j = 0; j < 4; j++) acc[i][j] = 0ull;

    float4 av = make_float4(0.f,0.f,0.f,0.f);
    if (m0 + a_mi < NRAY) av = *(const float4*)(g_eR + (size_t)(m0+a_mi)*HW + a_kq*4);
    float4 fv0 = *(const float4*)(fbase + (size_t)b_fi*HW + b_kq*8);
    float4 ev0 = *(const float4*)(epb + b_kq*8);
    float4 fv1 = *(const float4*)(fbase + (size_t)b_fi*HW + b_kq*8 + 4);
    float4 ev1 = *(const float4*)(epb + b_kq*8 + 4);
    {
        *(float2*)&As2[0][a_kq*4+0][2*a_mi] = make_float2(av.x, av.x);
        *(float2*)&As2[0][a_kq*4+1][2*a_mi] = make_float2(av.y, av.y);
        *(float2*)&As2[0][a_kq*4+2][2*a_mi] = make_float2(av.z, av.z);
        *(float2*)&As2[0][a_kq*4+3][2*a_mi] = make_float2(av.w, av.w);
        int kk = b_kq*8;
        Bs[0][kk+0][b_fi] = fv0.x*ev0.x; Bs[0][kk+1][b_fi] = fv0.y*ev0.y;
        Bs[0][kk+2][b_fi] = fv0.z*ev0.z; Bs[0][kk+3][b_fi] = fv0.w*ev0.w;
        Bs[0][kk+4][b_fi] = fv1.x*ev1.x; Bs[0][kk+5][b_fi] = fv1.y*ev1.y;
        Bs[0][kk+6][b_fi] = fv1.z*ev1.z; Bs[0][kk+7][b_fi] = fv1.w*ev1.w;
    }
    __syncthreads();

    #pragma unroll
    for (int it = 0; it < HW/TK; it++) {
        int buf = it & 1;
        if (it < HW/TK - 1) {
            int k0 = (it+1)*TK;
            float4 pav = make_float4(0.f,0.f,0.f,0.f);
            if (m0 + a_mi < NRAY) pav = *(const float4*)(g_eR + (size_t)(m0+a_mi)*HW + k0 + a_kq*4);
            float4 pf0 = *(const float4*)(fbase + (size_t)b_fi*HW + k0 + b_kq*8);
            float4 pe0 = *(const float4*)(epb + k0 + b_kq*8);
            float4 pf1 = *(const float4*)(fbase + (size_t)b_fi*HW + k0 + b_kq*8 + 4);
            float4 pe1 = *(const float4*)(epb + k0 + b_kq*8 + 4);
            int nb = buf ^ 1;
            *(float2*)&As2[nb][a_kq*4+0][2*a_mi] = make_float2(pav.x, pav.x);
            *(float2*)&As2[nb][a_kq*4+1][2*a_mi] = make_float2(pav.y, pav.y);
            *(float2*)&As2[nb][a_kq*4+2][2*a_mi] = make_float2(pav.z, pav.z);
            *(float2*)&As2[nb][a_kq*4+3][2*a_mi] = make_float2(pav.w, pav.w);
            int kk = b_kq*8;
            Bs[nb][kk+0][b_fi] = pf0.x*pe0.x; Bs[nb][kk+1][b_fi] = pf0.y*pe0.y;
            Bs[nb][kk+2][b_fi] = pf0.z*pe0.z; Bs[nb][kk+3][b_fi] = pf0.w*pe0.w;
            Bs[nb][kk+4][b_fi] = pf1.x*pe1.x; Bs[nb][kk+5][b_fi] = pf1.y*pe1.y;
            Bs[nb][kk+6][b_fi] = pf1.z*pe1.z; Bs[nb][kk+7][b_fi] = pf1.w*pe1.w;
        }
        #pragma unroll
        for (int kk = 0; kk < TK; kk++) {
            const ulonglong2* ap = (const ulonglong2*)&As2[buf][kk][ty*8];
            ulonglong2 aA = ap[0], aB = ap[1];
            const ulonglong2* bpt = (const ulonglong2*)&Bs[buf][kk][tx*8];
            ulonglong2 bA = bpt[0], bB = bpt[1];
            FMA_F32X2(acc[0][0], aA.x, bA.x, acc[0][0]);
            FMA_F32X2(acc[0][1], aA.x, bA.y, acc[0][1]);
            FMA_F32X2(acc[0][2], aA.x, bB.x, acc[0][2]);
            FMA_F32X2(acc[0][3], aA.x, bB.y, acc[0][3]);
            FMA_F32X2(acc[1][0], aA.y, bA.x, acc[1][0]);
            FMA_F32X2(acc[1][1], aA.y, bA.y, acc[1][1]);
            FMA_F32X2(acc[1][2], aA.y, bB.x, acc[1][2]);
            FMA_F32X2(acc[1][3], aA.y, bB.y, acc[1][3]);
            FMA_F32X2(acc[2][0], aB.x, bA.x, acc[2][0]);
            FMA_F32X2(acc[2][1], aB.x, bA.y, acc[2][1]);
            FMA_F32X2(acc[2][2], aB.x, bB.x, acc[2][2]);
            FMA_F32X2(acc[2][3], aB.x, bB.y, acc[2][3]);
            FMA_F32X2(acc[3][0], aB.y, bA.x, acc[3][0]);
            FMA_F32X2(acc[3][1], aB.y, bA.y, acc[3][1]);
            FMA_F32X2(acc[3][2], aB.y, bB.x, acc[3][2]);
            FMA_F32X2(acc[3][3], aB.y, bB.y, acc[3][3]);
        }
        __syncthreads();
    }

    float* gb = g_G + ((size_t)bp*NRAY + m0)*CC;
    #pragma unroll
    for (int i = 0; i < 4; i++) {
        int m = ty*4 + i;
        if (m0 + m < NRAY) {
            #pragma unroll
            for (int j = 0; j < 4; j++)
                *(float2*)&gb[(size_t)m*CC + tx*8 + j*2] = *(float2*)&acc[i][j];
        }
    }
}

// ---------------- merged outputs: grid_feats + attn ------------------------
__global__ void k_final(float* __restrict__ out) {
    int s = blockIdx.x, b = blockIdx.y, t = threadIdx.x;
    __shared__ int   si[NNB];
    __shared__ float se[NNB];
    __shared__ float sz;
    int base = (b*LL + s)*NNB;
    if (t < NNB) { si[t] = g_ind[base + t]; se[t] = g_eD[base + t]; }
    if (t == 0)  sz = g_invZ[b*LL + s];
    __syncthreads();
    float invZ = sz;
    if (t < CC) {
        float acc = 0.f;
        #pragma unroll
        for (int p = 0; p < NNB; p++)
            acc = fmaf(se[p], g_G[((size_t)(b*NNB + p)*NRAY + si[p])*CC + t], acc);
        out[(size_t)(b*LL + s)*CC + t] = acc * invZ;
    }
    float4* o = (float4*)(out + (size_t)BB*LL*CC + (size_t)base*HW);
    for (int i = t; i < NNB*(HW/4); i += 256) {
        int p = i >> 6, e = i & 63;
        float k = se[p] * invZ;
        float4 ep = ((const float4*)(g_eP + (size_t)(b*NNB + p)*HW))[e];
        float4 er = ((const float4*)(g_eR + (size_t)si[p]*HW))[e];
        o[i] = make_float4(k*ep.x*er.x, k*ep.y*er.y, k*ep.z*er.z, k*ep.w*er.w);
    }
}

// ---------------- launch -----------------------------------------------------
extern "C" void kernel_launch(void* const* d_in, const int* in_sizes, int n_in,
                              void* d_out, int out_size) {
    const float* bbox  = (const float*)d_in[0];
    const float* locs  = (const float*)d_in[1];
    const float* feats = (const float*)d_in[2];
    // d_in[3] = overhead_feat: cancels in the softmax -> unused
    const float* rays  = (const float*)d_in[4];
    const float* w1    = (const float*)d_in[5];
    const float* w2    = (const float*)d_in[7];
    const float* fw    = (const float*)d_in[9];
    float* out = (float*)d_out;

    k_RP<<<NRAY + BP, 256>>>(rays, feats, w1, w2, fw);
    k_T<<<NI/32, 256>>>();
    dim3 gg2(4, BB);
    k_geo<<<gg2, 256>>>(bbox, locs, w1, w2, fw);
    dim3 gg(6, NNB, BB);
    k_gemmG<<<gg, 256>>>(feats);
    dim3 go(LL, BB);
    k_final<<<go, 256>>>(out);
}

// round 6
// speedup vs baseline: 1.3017x; 1.3017x over previous
#include <cuda_runtime.h>
#include <math.h>

#define GSZ 32
#define LL  1024
#define BB  4
#define NNB 20
#define BP  (BB*NNB)     // 80
#define CC  128
#define HH  8
#define WW  32
#define HW  256
#define NRAY 360
#define NI   384         // padded ind count

// packed f32x2 FMA (Blackwell): one inst = 2 fp32 FMAs
#define FMA_F32X2(d,a,b,c) asm("fma.rn.f32x2 %0, %1, %2, %3;" : "=l"(d) : "l"(a), "l"(b), "l"(c))

// ---------------- scratch (device globals; no allocations) ----------------
__device__ float g_eR [NRAY*HW];
__device__ float g_eRT[HW*NI];          // [hw][ind], cols 360..383 garbage (never read)
__device__ float g_eP [BP*HW];
__device__ float g_ePT[HW*BP];          // [hw][bp]
__device__ float g_T  [NI*BP];          // [ind][bp], rows >=360 garbage (never read)
__device__ float g_G[(size_t)BP*NRAY*CC];   // 14.7 MB
__device__ int   g_ind[BB*LL*NNB];
__device__ float g_eD [BB*LL*NNB];
__device__ float g_invZ[BB*LL];

// ---------------- merged R/P tables: circular convs + fused exp ------------
__global__ void k_RP(const float* __restrict__ rays, const float* __restrict__ feats,
                     const float* __restrict__ w1, const float* __restrict__ w2,
                     const float* __restrict__ fw) {
    __shared__ float sbuf[3*HW];
    __shared__ float sw1[27], sw2[75];
    int t = threadIdx.x;
    int y = t >> 5, x = t & 31;

    if (blockIdx.x < NRAY) {
        int ind = blockIdx.x;
        for (int i = t; i < 3*HW; i += 256) sbuf[i] = rays[(size_t)ind*3*HW + i];
        if (t < 27) sw1[t] = w1[9  + t];   // conv1 channels 1..3
        if (t < 75) sw2[t] = w2[25 + t];   // conv2 channels 1..3
        __syncthreads();
        float a1 = 0.f, a2 = 0.f;
        #pragma unroll
        for (int c = 0; c < 3; c++) {
            const float* rc = sbuf + c*HW;
            #pragma unroll
            for (int ky = 0; ky < 3; ky++) {
                int yy = ((y + ky + 7) & 7) * 32;
                #pragma unroll
                for (int kx = 0; kx < 3; kx++)
                    a1 = fmaf(sw1[c*9 + ky*3 + kx], rc[yy + ((x + kx + 31) & 31)], a1);
            }
            #pragma unroll
            for (int ky = 0; ky < 5; ky++) {
                int yy = ((y + ky + 6) & 7) * 32;
                #pragma unroll
                for (int kx = 0; kx < 5; kx++)
                    a2 = fmaf(sw2[c*25 + ky*5 + kx], rc[yy + ((x + kx + 30) & 31)], a2);
            }
        }
        float e = expf(fw[0]*a1 + fw[1]*a2);
        g_eR [ind*HW + t]  = e;
        g_eRT[t*NI + ind]  = e;
    } else {
        int bp = blockIdx.x - NRAY;
        {
            const float* base = feats + (size_t)bp*CC*HW + t;
            float mx = -3.4e38f, sm = 0.f;
            #pragma unroll 8
            for (int c = 0; c < CC; c++) {
                float v = base[(size_t)c*HW];
                mx = fmaxf(mx, v);
                sm += v;
            }
            sbuf[t]      = mx;
            sbuf[HW + t] = sm * (1.0f/128.0f);
        }
        if (t < 18) sw1[t] = w1[4*9  + t];  // conv1 channels 4..5
        if (t < 50) sw2[t] = w2[4*25 + t];  // conv2 channels 4..5
        __syncthreads();
        float a1 = 0.f, a2 = 0.f;
        #pragma unroll
        for (int m = 0; m < 2; m++) {
            const float* pc = sbuf + m*HW;
            #pragma unroll
            for (int ky = 0; ky < 3; ky++) {
                int yy = ((y + ky + 7) & 7) * 32;
                #pragma unroll
                for (int kx = 0; kx < 3; kx++)
                    a1 = fmaf(sw1[m*9 + ky*3 + kx], pc[yy + ((x + kx + 31) & 31)], a1);
            }
            #pragma unroll
            for (int ky = 0; ky < 5; ky++) {
                int yy = ((y + ky + 6) & 7) * 32;
                #pragma unroll
                for (int kx = 0; kx < 5; kx++)
                    a2 = fmaf(sw2[m*25 + ky*5 + kx], pc[yy + ((x + kx + 30) & 31)], a2);
            }
        }
        float e = expf(fw[0]*a1 + fw[1]*a2);
        g_eP [bp*HW + t]  = e;
        g_ePT[t*BP + bp]  = e;
    }
}

// ---------------- T GEMM: T[ind,bp] = sum_hw eR[ind,hw]*eP[bp,hw] ----------
#define TTK 32
__global__ __launch_bounds__(256) void k_T() {
    __shared__ float sR[TTK][32];
    __shared__ float sP[TTK][BP];
    int ind0 = blockIdx.x * 32;
    int tid = threadIdx.x;
    int ti = tid & 31, gq = tid >> 5;
    float acc[10];
    #pragma unroll
    for (int j = 0; j < 10; j++) acc[j] = 0.f;

    for (int k0 = 0; k0 < HW; k0 += TTK) {
        {
            int kk = tid >> 3, q = tid & 7;
            *(float4*)&sR[kk][q*4] = *(const float4*)&g_eRT[(size_t)(k0+kk)*NI + ind0 + q*4];
        }
        for (int i = tid; i < TTK*(BP/4); i += 256) {
            int kk = i / (BP/4), q = i % (BP/4);
            *(float4*)&sP[kk][q*4] = *(const float4*)&g_ePT[(size_t)(k0+kk)*BP + q*4];
        }
        __syncthreads();
        #pragma unroll
        for (int kk = 0; kk < TTK; kk++) {
            float a = sR[kk][ti];
            #pragma unroll
            for (int j = 0; j < 10; j++)
                acc[j] = fmaf(a, sP[kk][gq*10 + j], acc[j]);
        }
        __syncthreads();
    }
    #pragma unroll
    for (int j = 0; j < 10; j++)
        g_T[(ind0 + ti)*BP + gq*10 + j] = acc[j];
}

// ---------------- geometry: ind, eD, Z per (b,s,p) --------------------------
__global__ void k_geo(const float* __restrict__ bbox, const float* __restrict__ locs,
                      const float* __restrict__ w1, const float* __restrict__ w2,
                      const float* __restrict__ fw) {
    int b = blockIdx.y;
    int s = blockIdx.x * 256 + threadIdx.x;
    int t = threadIdx.x;
    __shared__ float sT[NRAY*NNB];
    __shared__ float sl[NNB*2];
    __shared__ float sb[4];
    __shared__ float salpha;
    for (int i = t; i < NRAY*NNB; i += 256) {
        int ind = i / NNB, p = i % NNB;
        sT[i] = g_T[ind*BP + b*NNB + p];
    }
    if (t < NNB*2) sl[t] = locs[b*NNB*2 + t];
    if (t < 4)     sb[t] = bbox[b*4 + t];
    if (t == 0) {
        float s1 = 0.f, s2 = 0.f;
        for (int i = 0; i < 9; i++)  s1 += w1[i];
        for (int i = 0; i < 25; i++) s2 += w2[i];
        salpha = fw[0]*s1 + fw[1]*s2;
    }
    __syncthreads();
    int iy = s >> 5, ix = s & 31;
    float ystep = __fdiv_rn(sb[2] - sb[0], 31.0f);
    float xstep = __fdiv_rn(sb[3] - sb[1], 31.0f);
    float py = __fadd_rn(sb[0], __fmul_rn((float)iy, ystep));
    float px = __fadd_rn(sb[1], __fmul_rn((float)ix, xstep));
    float alpha = salpha;
    float Z = 0.f;
    int base = (b*LL + s)*NNB;
    for (int p = 0; p < NNB; p++) {
        float dy = py - sl[2*p];
        float dx = px - sl[2*p + 1];
        float D = sqrtf(__fadd_rn(__fadd_rn(__fmul_rn(dy,dy), __fmul_rn(dx,dx)), 1e-12f));
        float th = atan2f(dx, dy);
        if (th < 0.f) th += 6.283185307179586f;
        float deg = __fmul_rn(th, 57.29577951308232f);
        int ind = (int)rintf(deg);
        if (ind >= 360) ind -= 360;
        float eD = expf(alpha * D);
        g_ind[base + p] = ind;
        g_eD[base + p]  = eD;
        Z = fmaf(eD, sT[ind*NNB + p], Z);
    }
    g_invZ[b*LL + s] = 1.0f / Z;
}

// ---------------- G GEMM: 128x128 block, 8x8 thread tile, FFMA2 ------------
// G[bp, ind, f] = sum_hw eR[ind,hw] * feats[bp,f,hw] * eP[bp,hw]
#define GTM 128
#define GTK 16
#define GROW 132      // padded row (132*4B = 33*16B, keeps 16B alignment)

#define MMA_ROW(I, AV) do { unsigned long long pa_; \
    asm("mov.b64 %0, {%1, %1};" : "=l"(pa_) : "f"(AV)); \
    FMA_F32X2(acc[I][0], pa_, bA.x, acc[I][0]); \
    FMA_F32X2(acc[I][1], pa_, bA.y, acc[I][1]); \
    FMA_F32X2(acc[I][2], pa_, bB.x, acc[I][2]); \
    FMA_F32X2(acc[I][3], pa_, bB.y, acc[I][3]); } while(0)

__global__ __launch_bounds__(256, 2) void k_gemmG(const float* __restrict__ feats) {
    const int m0 = blockIdx.x * GTM;           // ind tile: 0,128,256
    const int bp = blockIdx.y;                 // (b,p)
    const float* fbase = feats + (size_t)bp*CC*HW;
    __shared__ __align__(16) float As[2][GTK][GROW];   // raw eR, [k][m]
    __shared__ __align__(16) float Bs[2][GTK][GROW];   // feats*eP, [k][f]
    __shared__ __align__(16) float seP[HW];

    int tid = threadIdx.x;
    int fm = tid >> 1, fq = tid & 1;           // fill: row (m or f), k-half
    int tx = tid & 15, ty = tid >> 4;          // compute: 8f group, 8m group

    int am = m0 + fm; if (am > NRAY-1) am = NRAY-1;   // clamp (rows >=360 never stored)
    const float* aptr = g_eR + (size_t)am*HW + fq*8;
    const float* bptr = fbase + (size_t)fm*HW + fq*8;

    if (tid < 64) ((float4*)seP)[tid] = ((const float4*)(g_eP + (size_t)bp*HW))[tid];

    unsigned long long acc[8][4];
    #pragma unroll
    for (int i = 0; i < 8; i++)
        #pragma unroll
        for (int j = 0; j < 4; j++) acc[i][j] = 0ull;

    // prologue: tile 0
    float4 a0 = *(const float4*)(aptr);
    float4 a1 = *(const float4*)(aptr + 4);
    float4 b0 = *(const float4*)(bptr);
    float4 b1 = *(const float4*)(bptr + 4);
    __syncthreads();    // seP visible
    {
        float4 e0 = *(const float4*)&seP[fq*8];
        float4 e1 = *(const float4*)&seP[fq*8 + 4];
        int kb = fq*8;
        As[0][kb+0][fm] = a0.x; As[0][kb+1][fm] = a0.y;
        As[0][kb+2][fm] = a0.z; As[0][kb+3][fm] = a0.w;
        As[0][kb+4][fm] = a1.x; As[0][kb+5][fm] = a1.y;
        As[0][kb+6][fm] = a1.z; As[0][kb+7][fm] = a1.w;
        Bs[0][kb+0][fm] = b0.x*e0.x; Bs[0][kb+1][fm] = b0.y*e0.y;
        Bs[0][kb+2][fm] = b0.z*e0.z; Bs[0][kb+3][fm] = b0.w*e0.w;
        Bs[0][kb+4][fm] = b1.x*e1.x; Bs[0][kb+5][fm] = b1.y*e1.y;
        Bs[0][kb+6][fm] = b1.z*e1.z; Bs[0][kb+7][fm] = b1.w*e1.w;
    }
    __syncthreads();

    #pragma unroll
    for (int it = 0; it < HW/GTK; it++) {
        int buf = it & 1;
        if (it < HW/GTK - 1) {
            int k0 = (it+1)*GTK;
            a0 = *(const float4*)(aptr + k0);
            a1 = *(const float4*)(aptr + k0 + 4);
            b0 = *(const float4*)(bptr + k0);
            b1 = *(const float4*)(bptr + k0 + 4);
        }
        #pragma unroll
        for (int kk = 0; kk < GTK; kk++) {
            float4 av0 = *(const float4*)&As[buf][kk][ty*8];
            float4 av1 = *(const float4*)&As[buf][kk][ty*8 + 4];
            ulonglong2 bA = *(const ulonglong2*)&Bs[buf][kk][tx*8];
            ulonglong2 bB = *(const ulonglong2*)&Bs[buf][kk][tx*8 + 4];
            MMA_ROW(0, av0.x); MMA_ROW(1, av0.y);
            MMA_ROW(2, av0.z); MMA_ROW(3, av0.w);
            MMA_ROW(4, av1.x); MMA_ROW(5, av1.y);
            MMA_ROW(6, av1.z); MMA_ROW(7, av1.w);
        }
        if (it < HW/GTK - 1) {
            int nb = buf ^ 1;
            int k0 = (it+1)*GTK;
            float4 e0 = *(const float4*)&seP[k0 + fq*8];
            float4 e1 = *(const float4*)&seP[k0 + fq*8 + 4];
            int kb = fq*8;
            As[nb][kb+0][fm] = a0.x; As[nb][kb+1][fm] = a0.y;
            As[nb][kb+2][fm] = a0.z; As[nb][kb+3][fm] = a0.w;
            As[nb][kb+4][fm] = a1.x; As[nb][kb+5][fm] = a1.y;
            As[nb][kb+6][fm] = a1.z; As[nb][kb+7][fm] = a1.w;
            Bs[nb][kb+0][fm] = b0.x*e0.x; Bs[nb][kb+1][fm] = b0.y*e0.y;
            Bs[nb][kb+2][fm] = b0.z*e0.z; Bs[nb][kb+3][fm] = b0.w*e0.w;
            Bs[nb][kb+4][fm] = b1.x*e1.x; Bs[nb][kb+5][fm] = b1.y*e1.y;
            Bs[nb][kb+6][fm] = b1.z*e1.z; Bs[nb][kb+7][fm] = b1.w*e1.w;
        }
        __syncthreads();
    }

    float* gb = g_G + ((size_t)bp*NRAY + m0)*CC + tx*8;
    #pragma unroll
    for (int i = 0; i < 8; i++) {
        int m = ty*8 + i;
        if (m0 + m < NRAY) {
            float* row = gb + (size_t)m*CC;
            #pragma unroll
            for (int j = 0; j < 4; j++)
                *(float2*)(row + j*2) = *(float2*)&acc[i][j];
        }
    }
}

// ---------------- merged outputs: grid_feats + attn ------------------------
__global__ void k_final(float* __restrict__ out) {
    int s = blockIdx.x, b = blockIdx.y, t = threadIdx.x;
    __shared__ int   si[NNB];
    __shared__ float se[NNB];
    __shared__ float sz;
    int base = (b*LL + s)*NNB;
    if (t < NNB) { si[t] = g_ind[base + t]; se[t] = g_eD[base + t]; }
    if (t == 0)  sz = g_invZ[b*LL + s];
    __syncthreads();
    float invZ = sz;
    if (t < CC) {
        float acc = 0.f;
        #pragma unroll
        for (int p = 0; p < NNB; p++)
            acc = fmaf(se[p], g_G[((size_t)(b*NNB + p)*NRAY + si[p])*CC + t], acc);
        out[(size_t)(b*LL + s)*CC + t] = acc * invZ;
    }
    float4* o = (float4*)(out + (size_t)BB*LL*CC + (size_t)base*HW);
    for (int i = t; i < NNB*(HW/4); i += 256) {
        int p = i >> 6, e = i & 63;
        float k = se[p] * invZ;
        float4 ep = ((const float4*)(g_eP + (size_t)(b*NNB + p)*HW))[e];
        float4 er = ((const float4*)(g_eR + (size_t)si[p]*HW))[e];
        o[i] = make_float4(k*ep.x*er.x, k*ep.y*er.y, k*ep.z*er.z, k*ep.w*er.w);
    }
}

// ---------------- launch -----------------------------------------------------
extern "C" void kernel_launch(void* const* d_in, const int* in_sizes, int n_in,
                              void* d_out, int out_size) {
    const float* bbox  = (const float*)d_in[0];
    const float* locs  = (const float*)d_in[1];
    const float* feats = (const float*)d_in[2];
    // d_in[3] = overhead_feat: cancels in the softmax -> unused
    const float* rays  = (const float*)d_in[4];
    const float* w1    = (const float*)d_in[5];
    const float* w2    = (const float*)d_in[7];
    const float* fw    = (const float*)d_in[9];
    float* out = (float*)d_out;

    k_RP<<<NRAY + BP, 256>>>(rays, feats, w1, w2, fw);
    k_T<<<NI/32, 256>>>();
    dim3 gg2(4, BB);
    k_geo<<<gg2, 256>>>(bbox, locs, w1, w2, fw);
    dim3 gg(3, BP);
    k_gemmG<<<gg, 256>>>(feats);
    dim3 go(LL, BB);
    k_final<<<go, 256>>>(out);
}

// round 8
// speedup vs baseline: 1.4203x; 1.0911x over previous
#include <cuda_runtime.h>
#include <math.h>

#define GSZ 32
#define LL  1024
#define BB  4
#define NNB 20
#define BP  (BB*NNB)     // 80
#define CC  128
#define HW  256
#define NRAY 360
#define NI   384

// packed f32x2 FMA (Blackwell): one inst = 2 fp32 FMAs
#define FMA_F32X2(d,a,b,c) asm("fma.rn.f32x2 %0, %1, %2, %3;" : "=l"(d) : "l"(a), "l"(b), "l"(c))

// ---------------- scratch (device globals; no allocations) ----------------
__device__ float g_eR [NRAY*HW];
__device__ float g_eRT[HW*NI];          // [hw][ind], cols 360..383 garbage (never read)
__device__ float g_eP [BP*HW];
__device__ float g_ePT[HW*BP];          // [hw][bp]
__device__ float g_T  [NI*BP];          // [ind][bp], rows >=360 garbage (never read)
__device__ float g_G[(size_t)BP*NRAY*CC];   // 14.7 MB
__device__ int   g_ind[BB*LL*NNB];
__device__ float g_eD [BB*LL*NNB];
__device__ float g_invZ[BB*LL];

// ---------------- merged R/P tables: circular convs + fused exp ------------
__global__ void k_RP(const float* __restrict__ rays, const float* __restrict__ feats,
                     const float* __restrict__ w1, const float* __restrict__ w2,
                     const float* __restrict__ fw) {
    __shared__ float sbuf[3*HW];
    __shared__ float sw1[27], sw2[75];
    int t = threadIdx.x;
    int y = t >> 5, x = t & 31;

    if (blockIdx.x < NRAY) {
        int ind = blockIdx.x;
        for (int i = t; i < 3*HW; i += 256) sbuf[i] = rays[(size_t)ind*3*HW + i];
        if (t < 27) sw1[t] = w1[9  + t];   // conv1 channels 1..3
        if (t < 75) sw2[t] = w2[25 + t];   // conv2 channels 1..3
        __syncthreads();
        float a1 = 0.f, a2 = 0.f;
        #pragma unroll
        for (int c = 0; c < 3; c++) {
            const float* rc = sbuf + c*HW;
            #pragma unroll
            for (int ky = 0; ky < 3; ky++) {
                int yy = ((y + ky + 7) & 7) * 32;
                #pragma unroll
                for (int kx = 0; kx < 3; kx++)
                    a1 = fmaf(sw1[c*9 + ky*3 + kx], rc[yy + ((x + kx + 31) & 31)], a1);
            }
            #pragma unroll
            for (int ky = 0; ky < 5; ky++) {
                int yy = ((y + ky + 6) & 7) * 32;
                #pragma unroll
                for (int kx = 0; kx < 5; kx++)
                    a2 = fmaf(sw2[c*25 + ky*5 + kx], rc[yy + ((x + kx + 30) & 31)], a2);
            }
        }
        float e = expf(fw[0]*a1 + fw[1]*a2);
        g_eR [ind*HW + t]  = e;
        g_eRT[t*NI + ind]  = e;
    } else {
        int bp = blockIdx.x - NRAY;
        {
            const float* base = feats + (size_t)bp*CC*HW + t;
            float mx = -3.4e38f, sm = 0.f;
            #pragma unroll 8
            for (int c = 0; c < CC; c++) {
                float v = base[(size_t)c*HW];
                mx = fmaxf(mx, v);
                sm += v;
            }
            sbuf[t]      = mx;
            sbuf[HW + t] = sm * (1.0f/128.0f);
        }
        if (t < 18) sw1[t] = w1[4*9  + t];  // conv1 channels 4..5
        if (t < 50) sw2[t] = w2[4*25 + t];  // conv2 channels 4..5
        __syncthreads();
        float a1 = 0.f, a2 = 0.f;
        #pragma unroll
        for (int m = 0; m < 2; m++) {
            const float* pc = sbuf + m*HW;
            #pragma unroll
            for (int ky = 0; ky < 3; ky++) {
                int yy = ((y + ky + 7) & 7) * 32;
                #pragma unroll
                for (int kx = 0; kx < 3; kx++)
                    a1 = fmaf(sw1[m*9 + ky*3 + kx], pc[yy + ((x + kx + 31) & 31)], a1);
            }
            #pragma unroll
            for (int ky = 0; ky < 5; ky++) {
                int yy = ((y + ky + 6) & 7) * 32;
                #pragma unroll
                for (int kx = 0; kx < 5; kx++)
                    a2 = fmaf(sw2[m*25 + ky*5 + kx], pc[yy + ((x + kx + 30) & 31)], a2);
            }
        }
        float e = expf(fw[0]*a1 + fw[1]*a2);
        g_eP [bp*HW + t]  = e;
        g_ePT[t*BP + bp]  = e;
    }
}

// ---------------- T GEMM: T[ind,bp] = sum_hw eR[ind,hw]*eP[bp,hw] ----------
#define TTK 32
__global__ __launch_bounds__(256) void k_T() {
    __shared__ float sR[TTK][32];
    __shared__ float sP[TTK][BP];
    int ind0 = blockIdx.x * 32;
    int tid = threadIdx.x;
    int ti = tid & 31, gq = tid >> 5;
    float acc[10];
    #pragma unroll
    for (int j = 0; j < 10; j++) acc[j] = 0.f;

    for (int k0 = 0; k0 < HW; k0 += TTK) {
        {
            int kk = tid >> 3, q = tid & 7;
            *(float4*)&sR[kk][q*4] = *(const float4*)&g_eRT[(size_t)(k0+kk)*NI + ind0 + q*4];
        }
        for (int i = tid; i < TTK*(BP/4); i += 256) {
            int kk = i / (BP/4), q = i % (BP/4);
            *(float4*)&sP[kk][q*4] = *(const float4*)&g_ePT[(size_t)(k0+kk)*BP + q*4];
        }
        __syncthreads();
        #pragma unroll
        for (int kk = 0; kk < TTK; kk++) {
            float a = sR[kk][ti];
            #pragma unroll
            for (int j = 0; j < 10; j++)
                acc[j] = fmaf(a, sP[kk][gq*10 + j], acc[j]);
        }
        __syncthreads();
    }
    #pragma unroll
    for (int j = 0; j < 10; j++)
        g_T[(ind0 + ti)*BP + gq*10 + j] = acc[j];
}

// ---------------- geometry: ind, eD, Z per (b,s,p) --------------------------
__global__ void k_geo(const float* __restrict__ bbox, const float* __restrict__ locs,
                      const float* __restrict__ w1, const float* __restrict__ w2,
                      const float* __restrict__ fw) {
    int b = blockIdx.y;
    int s = blockIdx.x * 256 + threadIdx.x;
    int t = threadIdx.x;
    __shared__ float sT[NRAY*NNB];
    __shared__ float sl[NNB*2];
    __shared__ float sb[4];
    __shared__ float salpha;
    for (int i = t; i < NRAY*NNB; i += 256) {
        int ind = i / NNB, p = i % NNB;
        sT[i] = g_T[ind*BP + b*NNB + p];
    }
    if (t < NNB*2) sl[t] = locs[b*NNB*2 + t];
    if (t < 4)     sb[t] = bbox[b*4 + t];
    if (t == 0) {
        float s1 = 0.f, s2 = 0.f;
        for (int i = 0; i < 9; i++)  s1 += w1[i];
        for (int i = 0; i < 25; i++) s2 += w2[i];
        salpha = fw[0]*s1 + fw[1]*s2;
    }
    __syncthreads();
    int iy = s >> 5, ix = s & 31;
    float ystep = __fdiv_rn(sb[2] - sb[0], 31.0f);
    float xstep = __fdiv_rn(sb[3] - sb[1], 31.0f);
    float py = __fadd_rn(sb[0], __fmul_rn((float)iy, ystep));
    float px = __fadd_rn(sb[1], __fmul_rn((float)ix, xstep));
    float alpha = salpha;
    float Z = 0.f;
    int base = (b*LL + s)*NNB;
    for (int p = 0; p < NNB; p++) {
        float dy = py - sl[2*p];
        float dx = px - sl[2*p + 1];
        float D = sqrtf(__fadd_rn(__fadd_rn(__fmul_rn(dy,dy), __fmul_rn(dx,dx)), 1e-12f));
        float th = atan2f(dx, dy);
        if (th < 0.f) th += 6.283185307179586f;
        float deg = __fmul_rn(th, 57.29577951308232f);
        int ind = (int)rintf(deg);
        if (ind >= 360) ind -= 360;
        float eD = expf(alpha * D);
        g_ind[base + p] = ind;
        g_eD[base + p]  = eD;
        Z = fmaf(eD, sT[ind*NNB + p], Z);
    }
    g_invZ[b*LL + s] = 1.0f / Z;
}

// ---------------- G GEMM: 128m x 64n block, 8x4 thread tile, FFMA2 ----------
// G[bp, ind, f] = sum_hw eR[ind,hw] * feats[bp,f,hw] * eP[bp,hw]
#define GTM 128
#define GTN 64
#define GTK 16
#define GROWA 132      // padded A row
#define GROWB 68       // padded B row

#define MMA_ROW4(I, AV) do { unsigned long long pa_; \
    asm("mov.b64 %0, {%1, %1};" : "=l"(pa_) : "f"(AV)); \
    FMA_F32X2(acc[I][0], pa_, bA.x, acc[I][0]); \
    FMA_F32X2(acc[I][1], pa_, bA.y, acc[I][1]); } while(0)

__global__ __launch_bounds__(256, 3) void k_gemmG(const float* __restrict__ feats) {
    const int m0 = blockIdx.x * GTM;           // ind tile: 0,128,256
    const int n0 = blockIdx.y * GTN;           // f tile within bp: 0,64
    const int bp = blockIdx.z;                 // (b,p)
    const float* fbase = feats + ((size_t)bp*CC + n0)*HW;
    __shared__ __align__(16) float As[2][GTK][GROWA];   // raw eR, [k][m]
    __shared__ __align__(16) float Bs[2][GTK][GROWB];   // feats*eP, [k][f]
    __shared__ __align__(16) float seP[HW];

    int tid = threadIdx.x;
    int fm = tid >> 1, fq = tid & 1;           // A fill: row, k-half (8 each)
    int bfm = tid >> 2, bfq = tid & 3;         // B fill: row, k-quad (4 each)
    int tx = tid & 15, ty = tid >> 4;          // compute: 16 n-groups x 16 m-groups

    int am = m0 + fm; if (am > NRAY-1) am = NRAY-1;   // clamp (rows >=360 never stored)
    const float* aptr = g_eR + (size_t)am*HW + fq*8;
    const float* bptr = fbase + (size_t)bfm*HW + bfq*4;

    if (tid < 64) ((float4*)seP)[tid] = ((const float4*)(g_eP + (size_t)bp*HW))[tid];

    unsigned long long acc[8][2];
    #pragma unroll
    for (int i = 0; i < 8; i++) { acc[i][0] = 0ull; acc[i][1] = 0ull; }

    // prologue: tile 0
    float4 a0 = *(const float4*)(aptr);
    float4 a1 = *(const float4*)(aptr + 4);
    float4 b0 = *(const float4*)(bptr);
    __syncthreads();    // seP visible
    {
        float4 e0 = *(const float4*)&seP[bfq*4];
        int kb = fq*8;
        As[0][kb+0][fm] = a0.x; As[0][kb+1][fm] = a0.y;
        As[0][kb+2][fm] = a0.z; As[0][kb+3][fm] = a0.w;
        As[0][kb+4][fm] = a1.x; As[0][kb+5][fm] = a1.y;
        As[0][kb+6][fm] = a1.z; As[0][kb+7][fm] = a1.w;
        int kc = bfq*4;
        Bs[0][kc+0][bfm] = b0.x*e0.x; Bs[0][kc+1][bfm] = b0.y*e0.y;
        Bs[0][kc+2][bfm] = b0.z*e0.z; Bs[0][kc+3][bfm] = b0.w*e0.w;
    }
    __syncthreads();

    #pragma unroll
    for (int it = 0; it < HW/GTK; it++) {
        int buf = it & 1;
        if (it < HW/GTK - 1) {
            int k0 = (it+1)*GTK;
            a0 = *(const float4*)(aptr + k0);
            a1 = *(const float4*)(aptr + k0 + 4);
            b0 = *(const float4*)(bptr + k0);
        }
        #pragma unroll
        for (int kk = 0; kk < GTK; kk++) {
            float4 av0 = *(const float4*)&As[buf][kk][ty*8];
            float4 av1 = *(const float4*)&As[buf][kk][ty*8 + 4];
            ulonglong2 bA = *(const ulonglong2*)&Bs[buf][kk][tx*4];
            MMA_ROW4(0, av0.x); MMA_ROW4(1, av0.y);
            MMA_ROW4(2, av0.z); MMA_ROW4(3, av0.w);
            MMA_ROW4(4, av1.x); MMA_ROW4(5, av1.y);
            MMA_ROW4(6, av1.z); MMA_ROW4(7, av1.w);
        }
        if (it < HW/GTK - 1) {
            int nb = buf ^ 1;
            int k0 = (it+1)*GTK;
            float4 e0 = *(const float4*)&seP[k0 + bfq*4];
            int kb = fq*8;
            As[nb][kb+0][fm] = a0.x; As[nb][kb+1][fm] = a0.y;
            As[nb][kb+2][fm] = a0.z; As[nb][kb+3][fm] = a0.w;
            As[nb][kb+4][fm] = a1.x; As[nb][kb+5][fm] = a1.y;
            As[nb][kb+6][fm] = a1.z; As[nb][kb+7][fm] = a1.w;
            int kc = bfq*4;
            Bs[nb][kc+0][bfm] = b0.x*e0.x; Bs[nb][kc+1][bfm] = b0.y*e0.y;
            Bs[nb][kc+2][bfm] = b0.z*e0.z; Bs[nb][kc+3][bfm] = b0.w*e0.w;
        }
        __syncthreads();
    }

    float* gb = g_G + ((size_t)bp*NRAY + m0)*CC + n0 + tx*4;
    #pragma unroll
    for (int i = 0; i < 8; i++) {
        int m = ty*8 + i;
        if (m0 + m < NRAY) {
            float* row = gb + (size_t)m*CC;
            *(float2*)(row)     = *(float2*)&acc[i][0];
            *(float2*)(row + 2) = *(float2*)&acc[i][1];
        }
    }
}

// ---------------- merged outputs: grid_feats + attn ------------------------
__global__ void k_final(float* __restrict__ out) {
    int s = blockIdx.x, b = blockIdx.y, t = threadIdx.x;
    __shared__ int   si[NNB];
    __shared__ float se[NNB];
    __shared__ float sz;
    int base = (b*LL + s)*NNB;
    if (t < NNB) { si[t] = g_ind[base + t]; se[t] = g_eD[base + t]; }
    if (t == 0)  sz = g_invZ[b*LL + s];
    __syncthreads();
    float invZ = sz;
    if (t < CC) {
        float acc = 0.f;
        #pragma unroll
        for (int p = 0; p < NNB; p++)
            acc = fmaf(se[p], g_G[((size_t)(b*NNB + p)*NRAY + si[p])*CC + t], acc);
        out[(size_t)(b*LL + s)*CC + t] = acc * invZ;
    }
    float4* o = (float4*)(out + (size_t)BB*LL*CC + (size_t)base*HW);
    for (int i = t; i < NNB*(HW/4); i += 256) {
        int p = i >> 6, e = i & 63;
        float k = se[p] * invZ;
        float4 ep = ((const float4*)(g_eP + (size_t)(b*NNB + p)*HW))[e];
        float4 er = ((const float4*)(g_eR + (size_t)si[p]*HW))[e];
        o[i] = make_float4(k*ep.x*er.x, k*ep.y*er.y, k*ep.z*er.z, k*ep.w*er.w);
    }
}

// ---------------- launch -----------------------------------------------------
extern "C" void kernel_launch(void* const* d_in, const int* in_sizes, int n_in,
                              void* d_out, int out_size) {
    const float* bbox  = (const float*)d_in[0];
    const float* locs  = (const float*)d_in[1];
    const float* feats = (const float*)d_in[2];
    // d_in[3] = overhead_feat: cancels in the softmax -> unused
    const float* rays  = (const float*)d_in[4];
    const float* w1    = (const float*)d_in[5];
    const float* w2    = (const float*)d_in[7];
    const float* fw    = (const float*)d_in[9];
    float* out = (float*)d_out;

    k_RP<<<NRAY + BP, 256>>>(rays, feats, w1, w2, fw);
    k_T<<<NI/32, 256>>>();
    dim3 gg2(4, BB);
    k_geo<<<gg2, 256>>>(bbox, locs, w1, w2, fw);
    dim3 gg(3, 2, BP);
    k_gemmG<<<gg, 256>>>(feats);
    dim3 go(LL, BB);
    k_final<<<go, 256>>>(out);
}

// round 10
// speedup vs baseline: 1.4261x; 1.0041x over previous
#include <cuda_runtime.h>
#include <math.h>
#include <stdint.h>

#define GSZ 32
#define LL  1024
#define BB  4
#define NNB 20
#define BP  (BB*NNB)     // 80
#define CC  128
#define HW  256
#define NRAY 360
#define NI   384

// packed f32x2 FMA (Blackwell): one inst = 2 fp32 FMAs
#define FMA_F32X2(d,a,b,c) asm("fma.rn.f32x2 %0, %1, %2, %3;" : "=l"(d) : "l"(a), "l"(b), "l"(c))
// cp.async 16B global->shared (L1 bypass)
#define CP16(dst, src) asm volatile("cp.async.cg.shared.global [%0], [%1], 16;" :: "r"(dst), "l"(src))
#define CP_COMMIT()    asm volatile("cp.async.commit_group;")
#define CP_WAIT_ALL()  asm volatile("cp.async.wait_group 0;")

__device__ __forceinline__ uint32_t smem_u32(const void* p) {
    uint32_t a;
    asm("{ .reg .u64 t; cvta.to.shared.u64 t, %1; cvt.u32.u64 %0, t; }" : "=r"(a) : "l"(p));
    return a;
}

// ---------------- scratch (device globals; no allocations) ----------------
__device__ float g_eR [NRAY*HW];
__device__ float g_eRT[HW*NI];          // [hw][ind], cols 360..383 stay zero (never written)
__device__ float g_eP [BP*HW];
__device__ float g_ePT[HW*BP];          // [hw][bp]
__device__ float g_BT [(size_t)BP*HW*CC];  // [bp][k][f] = feats*eP transposed, 10.5 MB
__device__ float g_T  [NI*BP];          // [ind][bp], rows >=360 garbage (never read)
__device__ float g_G[(size_t)BP*NRAY*CC];   // 14.7 MB
__device__ int   g_ind[BB*LL*NNB];
__device__ float g_eD [BB*LL*NNB];
__device__ float g_invZ[BB*LL];

// ---------------- merged R/P tables: circular convs + fused exp ------------
__global__ void k_RP(const float* __restrict__ rays, const float* __restrict__ feats,
                     const float* __restrict__ w1, const float* __restrict__ w2,
                     const float* __restrict__ fw) {
    __shared__ float sbuf[3*HW];
    __shared__ float sw1[27], sw2[75];
    int t = threadIdx.x;
    int y = t >> 5, x = t & 31;

    if (blockIdx.x < NRAY) {
        int ind = blockIdx.x;
        for (int i = t; i < 3*HW; i += 256) sbuf[i] = rays[(size_t)ind*3*HW + i];
        if (t < 27) sw1[t] = w1[9  + t];   // conv1 channels 1..3
        if (t < 75) sw2[t] = w2[25 + t];   // conv2 channels 1..3
        __syncthreads();
        float a1 = 0.f, a2 = 0.f;
        #pragma unroll
        for (int c = 0; c < 3; c++) {
            const float* rc = sbuf + c*HW;
            #pragma unroll
            for (int ky = 0; ky < 3; ky++) {
                int yy = ((y + ky + 7) & 7) * 32;
                #pragma unroll
                for (int kx = 0; kx < 3; kx++)
                    a1 = fmaf(sw1[c*9 + ky*3 + kx], rc[yy + ((x + kx + 31) & 31)], a1);
            }
            #pragma unroll
            for (int ky = 0; ky < 5; ky++) {
                int yy = ((y + ky + 6) & 7) * 32;
                #pragma unroll
                for (int kx = 0; kx < 5; kx++)
                    a2 = fmaf(sw2[c*25 + ky*5 + kx], rc[yy + ((x + kx + 30) & 31)], a2);
            }
        }
        float e = expf(fw[0]*a1 + fw[1]*a2);
        g_eR [ind*HW + t]  = e;
        g_eRT[t*NI + ind]  = e;
    } else {
        int bp = blockIdx.x - NRAY;
        {
            const float* base = feats + (size_t)bp*CC*HW + t;
            float mx = -3.4e38f, sm = 0.f;
            #pragma unroll 8
            for (int c = 0; c < CC; c++) {
                float v = base[(size_t)c*HW];
                mx = fmaxf(mx, v);
                sm += v;
            }
            sbuf[t]      = mx;
            sbuf[HW + t] = sm * (1.0f/128.0f);
        }
        if (t < 18) sw1[t] = w1[4*9  + t];  // conv1 channels 4..5
        if (t < 50) sw2[t] = w2[4*25 + t];  // conv2 channels 4..5
        __syncthreads();
        float a1 = 0.f, a2 = 0.f;
        #pragma unroll
        for (int m = 0; m < 2; m++) {
            const float* pc = sbuf + m*HW;
            #pragma unroll
            for (int ky = 0; ky < 3; ky++) {
                int yy = ((y + ky + 7) & 7) * 32;
                #pragma unroll
                for (int kx = 0; kx < 3; kx++)
                    a1 = fmaf(sw1[m*9 + ky*3 + kx], pc[yy + ((x + kx + 31) & 31)], a1);
            }
            #pragma unroll
            for (int ky = 0; ky < 5; ky++) {
                int yy = ((y + ky + 6) & 7) * 32;
                #pragma unroll
                for (int kx = 0; kx < 5; kx++)
                    a2 = fmaf(sw2[m*25 + ky*5 + kx], pc[yy + ((x + kx + 30) & 31)], a2);
            }
        }
        float e = expf(fw[0]*a1 + fw[1]*a2);
        g_eP [bp*HW + t]  = e;
        g_ePT[t*BP + bp]  = e;
    }
}

// ---------------- B transpose + premultiply: g_BT[bp][k][f] = feats*eP ------
__global__ __launch_bounds__(256) void k_BT(const float* __restrict__ feats) {
    __shared__ float s[32][132];
    int bp = blockIdx.x >> 3, kt = blockIdx.x & 7;
    int k0 = kt*32;
    int tid = threadIdx.x;
    int f = tid >> 1, kq = tid & 1;
    const float* fb = feats + ((size_t)bp*CC + f)*HW + k0 + kq*16;
    const float* ep = g_eP + (size_t)bp*HW + k0 + kq*16;
    #pragma unroll
    for (int q = 0; q < 4; q++) {
        float4 v = *(const float4*)(fb + q*4);
        float4 e = *(const float4*)(ep + q*4);
        int kl = kq*16 + q*4;
        s[kl+0][f] = v.x*e.x; s[kl+1][f] = v.y*e.y;
        s[kl+2][f] = v.z*e.z; s[kl+3][f] = v.w*e.w;
    }
    __syncthreads();
    #pragma unroll
    for (int q = 0; q < 4; q++) {
        int idx = q*256 + tid;
        int r = idx >> 5, cg = idx & 31;
        *(float4*)&g_BT[((size_t)bp*HW + k0 + r)*CC + cg*4] = *(float4*)&s[r][cg*4];
    }
}

// ---------------- T GEMM: T[ind,bp] = sum_hw eR[ind,hw]*eP[bp,hw] ----------
#define TTK 32
__global__ __launch_bounds__(256) void k_T() {
    __shared__ float sR[TTK][32];
    __shared__ float sP[TTK][BP];
    int ind0 = blockIdx.x * 32;
    int tid = threadIdx.x;
    int ti = tid & 31, gq = tid >> 5;
    float acc[10];
    #pragma unroll
    for (int j = 0; j < 10; j++) acc[j] = 0.f;

    for (int k0 = 0; k0 < HW; k0 += TTK) {
        {
            int kk = tid >> 3, q = tid & 7;
            *(float4*)&sR[kk][q*4] = *(const float4*)&g_eRT[(size_t)(k0+kk)*NI + ind0 + q*4];
        }
        for (int i = tid; i < TTK*(BP/4); i += 256) {
            int kk = i / (BP/4), q = i % (BP/4);
            *(float4*)&sP[kk][q*4] = *(const float4*)&g_ePT[(size_t)(k0+kk)*BP + q*4];
        }
        __syncthreads();
        #pragma unroll
        for (int kk = 0; kk < TTK; kk++) {
            float a = sR[kk][ti];
            #pragma unroll
            for (int j = 0; j < 10; j++)
                acc[j] = fmaf(a, sP[kk][gq*10 + j], acc[j]);
        }
        __syncthreads();
    }
    #pragma unroll
    for (int j = 0; j < 10; j++)
        g_T[(ind0 + ti)*BP + gq*10 + j] = acc[j];
}

// ---------------- geometry: ind, eD, Z per (b,s,p) --------------------------
__global__ void k_geo(const float* __restrict__ bbox, const float* __restrict__ locs,
                      const float* __restrict__ w1, const float* __restrict__ w2,
                      const float* __restrict__ fw) {
    int b = blockIdx.y;
    int s = blockIdx.x * 256 + threadIdx.x;
    int t = threadIdx.x;
    __shared__ float sT[NRAY*NNB];
    __shared__ float sl[NNB*2];
    __shared__ float sb[4];
    __shared__ float salpha;
    for (int i = t; i < NRAY*NNB; i += 256) {
        int ind = i / NNB, p = i % NNB;
        sT[i] = g_T[ind*BP + b*NNB + p];
    }
    if (t < NNB*2) sl[t] = locs[b*NNB*2 + t];
    if (t < 4)     sb[t] = bbox[b*4 + t];
    if (t == 0) {
        float s1 = 0.f, s2 = 0.f;
        for (int i = 0; i < 9; i++)  s1 += w1[i];
        for (int i = 0; i < 25; i++) s2 += w2[i];
        salpha = fw[0]*s1 + fw[1]*s2;
    }
    __syncthreads();
    int iy = s >> 5, ix = s & 31;
    float ystep = __fdiv_rn(sb[2] - sb[0], 31.0f);
    float xstep = __fdiv_rn(sb[3] - sb[1], 31.0f);
    float py = __fadd_rn(sb[0], __fmul_rn((float)iy, ystep));
    float px = __fadd_rn(sb[1], __fmul_rn((float)ix, xstep));
    float alpha = salpha;
    float Z = 0.f;
    int base = (b*LL + s)*NNB;
    for (int p = 0; p < NNB; p++) {
        float dy = py - sl[2*p];
        float dx = px - sl[2*p + 1];
        float D = sqrtf(__fadd_rn(__fadd_rn(__fmul_rn(dy,dy), __fmul_rn(dx,dx)), 1e-12f));
        float th = atan2f(dx, dy);
        if (th < 0.f) th += 6.283185307179586f;
        float deg = __fmul_rn(th, 57.29577951308232f);
        int ind = (int)rintf(deg);
        if (ind >= 360) ind -= 360;
        float eD = expf(alpha * D);
        g_ind[base + p] = ind;
        g_eD[base + p]  = eD;
        Z = fmaf(eD, sT[ind*NNB + p], Z);
    }
    g_invZ[b*LL + s] = 1.0f / Z;
}

// ---------------- G GEMM: cp.async double-buffered, 128x64, 8x4, FFMA2 ------
// G[bp, ind, f] = sum_k eRT[k][ind] * g_BT[bp][k][f]
#define KC 32

#define MMA_ROW4(I, AV) do { unsigned long long pa_; \
    asm("mov.b64 %0, {%1, %1};" : "=l"(pa_) : "f"(AV)); \
    FMA_F32X2(acc[I][0], pa_, bA.x, acc[I][0]); \
    FMA_F32X2(acc[I][1], pa_, bA.y, acc[I][1]); } while(0)

__global__ __launch_bounds__(256, 4) void k_gemmG() {
    __shared__ __align__(16) float sA[2][KC][128];   // [k][m]: 1024 16B pieces
    __shared__ __align__(16) float sB[2][KC][64];    // [k][f]: 512 16B pieces
    const int m0 = blockIdx.x * 128;   // ind tile: 0,128,256
    const int n0 = blockIdx.y * 64;    // f tile: 0,64
    const int bp = blockIdx.z;
    int tid = threadIdx.x;
    int tx = tid & 15, ty = tid >> 4;

    // A: piece i = tid + q*256 -> row (tid>>5)+8q (0..31), col-piece tid&31.
    // 32 consecutive threads fill one full 128-float row => coalesced 128B lines.
    int ar0 = tid >> 5, acp = tid & 31;
    const float* aS = g_eRT + (size_t)ar0*NI + m0 + acp*4;
    uint32_t aD[2][4];
    #pragma unroll
    for (int q = 0; q < 4; q++) {
        aD[0][q] = smem_u32(&sA[0][ar0 + q*8][acp*4]);
        aD[1][q] = smem_u32(&sA[1][ar0 + q*8][acp*4]);
    }
    // B: 512 pieces, 2 per thread: idx = tid and tid+256
    int b0kk = tid >> 4, b0j = tid & 15;
    int b1kk = (tid + 256) >> 4;
    const float* b0S = g_BT + ((size_t)bp*HW + b0kk)*CC + n0 + b0j*4;
    const float* b1S = g_BT + ((size_t)bp*HW + b1kk)*CC + n0 + b0j*4;
    uint32_t b0D[2] = { smem_u32(&sB[0][b0kk][b0j*4]), smem_u32(&sB[1][b0kk][b0j*4]) };
    uint32_t b1D[2] = { smem_u32(&sB[0][b1kk][b0j*4]), smem_u32(&sB[1][b1kk][b0j*4]) };

    unsigned long long acc[8][2];
    #pragma unroll
    for (int i = 0; i < 8; i++) { acc[i][0] = 0ull; acc[i][1] = 0ull; }

    // prologue: chunk 0 into buffer 0
    #pragma unroll
    for (int q = 0; q < 4; q++) CP16(aD[0][q], aS + (size_t)q*8*NI);
    CP16(b0D[0], b0S); CP16(b1D[0], b1S);
    CP_COMMIT();

    #pragma unroll
    for (int c = 0; c < HW/KC; c++) {
        int buf = c & 1;
        CP_WAIT_ALL();
        __syncthreads();
        if (c < HW/KC - 1) {
            int nb = buf ^ 1;
            size_t ka = (size_t)(c+1)*KC*NI;
            size_t kb = (size_t)(c+1)*KC*CC;
            #pragma unroll
            for (int q = 0; q < 4; q++) CP16(aD[nb][q], aS + ka + (size_t)q*8*NI);
            CP16(b0D[nb], b0S + kb); CP16(b1D[nb], b1S + kb);
            CP_COMMIT();
        }
        #pragma unroll
        for (int kk = 0; kk < KC; kk++) {
            float4 av0 = *(const float4*)&sA[buf][kk][ty*8];
            float4 av1 = *(const float4*)&sA[buf][kk][ty*8 + 4];
            ulonglong2 bA = *(const ulonglong2*)&sB[buf][kk][tx*4];
            MMA_ROW4(0, av0.x); MMA_ROW4(1, av0.y);
            MMA_ROW4(2, av0.z); MMA_ROW4(3, av0.w);
            MMA_ROW4(4, av1.x); MMA_ROW4(5, av1.y);
            MMA_ROW4(6, av1.z); MMA_ROW4(7, av1.w);
        }
        __syncthreads();
    }

    float* gb = g_G + ((size_t)bp*NRAY + m0)*CC + n0 + tx*4;
    #pragma unroll
    for (int i = 0; i < 8; i++) {
        int m = ty*8 + i;
        if (m0 + m < NRAY) {
            float* row = gb + (size_t)m*CC;
            *(float2*)(row)     = *(float2*)&acc[i][0];
            *(float2*)(row + 2) = *(float2*)&acc[i][1];
        }
    }
}

// ---------------- merged outputs: grid_feats + attn ------------------------
__global__ void k_final(float* __restrict__ out) {
    int s = blockIdx.x, b = blockIdx.y, t = threadIdx.x;
    __shared__ int   si[NNB];
    __shared__ float se[NNB];
    __shared__ float sz;
    int base = (b*LL + s)*NNB;
    if (t < NNB) { si[t] = g_ind[base + t]; se[t] = g_eD[base + t]; }
    if (t == 0)  sz = g_invZ[b*LL + s];
    __syncthreads();
    float invZ = sz;
    if (t < CC) {
        float acc = 0.f;
        #pragma unroll
        for (int p = 0; p < NNB; p++)
            acc = fmaf(se[p], g_G[((size_t)(b*NNB + p)*NRAY + si[p])*CC + t], acc);
        out[(size_t)(b*LL + s)*CC + t] = acc * invZ;
    }
    float4* o = (float4*)(out + (size_t)BB*LL*CC + (size_t)base*HW);
    for (int i = t; i < NNB*(HW/4); i += 256) {
        int p = i >> 6, e = i & 63;
        float k = se[p] * invZ;
        float4 ep = ((const float4*)(g_eP + (size_t)(b*NNB + p)*HW))[e];
        float4 er = ((const float4*)(g_eR + (size_t)si[p]*HW))[e];
        o[i] = make_float4(k*ep.x*er.x, k*ep.y*er.y, k*ep.z*er.z, k*ep.w*er.w);
    }
}

// ---------------- launch -----------------------------------------------------
extern "C" void kernel_launch(void* const* d_in, const int* in_sizes, int n_in,
                              void* d_out, int out_size) {
    const float* bbox  = (const float*)d_in[0];
    const float* locs  = (const float*)d_in[1];
    const float* feats = (const float*)d_in[2];
    // d_in[3] = overhead_feat: cancels in the softmax -> unused
    const float* rays  = (const float*)d_in[4];
    const float* w1    = (const float*)d_in[5];
    const float* w2    = (const float*)d_in[7];
    const float* fw    = (const float*)d_in[9];
    float* out = (float*)d_out;

    k_RP<<<NRAY + BP, 256>>>(rays, feats, w1, w2, fw);
    k_BT<<<BP*8, 256>>>(feats);
    k_T<<<NI/32, 256>>>();
    dim3 gg2(4, BB);
    k_geo<<<gg2, 256>>>(bbox, locs, w1, w2, fw);
    dim3 gg(3, 2, BP);
    k_gemmG<<<gg, 256>>>();
    dim3 go(LL, BB);
    k_final<<<go, 256>>>(out);
}